// round 10
// baseline (speedup 1.0000x reference)
#include <cuda_runtime.h>

// 3D life-like CA step (26-neighbor count, periodic wrap) on a 384^3 float
// grid; output = first out_size (=64) cells of the flattened new grid,
// i.e. cells (x=0, y=0, z=i).
//
// FINAL KERNEL — measured at the launch-overhead floor. Six bench rounds
// across launch shapes (1x64, 2x32, 1x32x2cells) and 27-54 loads/thread
// all land in 4.51-4.61us (+-1.5 timer quanta); the identical binary
// varies 3.7-4.0us kernel-dur run-to-run. DRAM 0.0%, L2 0.3%, pipes 0.0%.
//
// Latency-optimal structure:
//  - single block, 64 threads, one cell each (best-measured shape, 4.512us)
//  - 27 independent grid loads per thread, front-batched -> exactly one
//    memory round trip on the critical path
//  - rule tables loaded concurrently by lanes 0..26, packed into register
//    bitmasks via one ballot pair -> lookup is ALU-only, no dependent trip
//  - x=y=0 row offsets are compile-time constants; no clamps (0/1 grid
//    makes the neighbor count an exact int in [0,26])
// Rejected by cycle model: smem staging (+BAR/LDS), shuffle exchange
// (+SHFL 26cyc after load return), vector loads (per-lane misalignment).
//
// Inputs: d_in[0] grid f32[384^3], d_in[1] survive int32[27],
//         d_in[2] birth int32[27], d_in[3] num_models (unused)
// Output: float32 [out_size]

#define DIM 384

__global__ __launch_bounds__(64, 1)
void ca_first_cells_kernel(const float* __restrict__ grid,
                           const int* __restrict__ survive_mask,
                           const int* __restrict__ birth_mask,
                           float* __restrict__ out) {
    const int i = threadIdx.x;            // cell index, 0..63
    const unsigned lane = (unsigned)i & 31u;

    // Rule-table loads first: independent, resolve inside the same memory
    // round trip as the grid loads.
    const unsigned mi = lane < 27u ? lane : 26u;
    const int sv = survive_mask[mi];
    const int bv = birth_mask[mi];

    // Cell (0, 0, z=i). Low-side wrap only at z=0; high side never wraps
    // (i <= 63 << DIM-1).
    const int z = i;
    const int zm1 = (z == 0) ? (DIM - 1) : (z - 1);
    const int zp1 = z + 1;

    // 9 (x,y)-row base offsets for x=0, y=0: compile-time constants.
    const int rowoff[9] = {
        (DIM - 1) * DIM * DIM + (DIM - 1) * DIM,
        (DIM - 1) * DIM * DIM,
        (DIM - 1) * DIM * DIM + DIM,
        (DIM - 1) * DIM,
        0,
        DIM,
        DIM * DIM + (DIM - 1) * DIM,
        DIM * DIM,
        DIM * DIM + DIM,
    };

    // 27 independent loads, front-batched for max MLP (one latency round).
    float v[27];
#pragma unroll
    for (int r = 0; r < 9; r++) {
        v[r * 3 + 0] = __ldg(&grid[rowoff[r] + zm1]);
        v[r * 3 + 1] = __ldg(&grid[rowoff[r] + z]);
        v[r * 3 + 2] = __ldg(&grid[rowoff[r] + zp1]);
    }

    // Pack rule tables into register bitmasks (per-warp ballots); overlaps
    // with the in-flight grid loads.
    const unsigned valid = (lane < 27u);
    const unsigned sbits = __ballot_sync(0xffffffffu, (sv != 0) & valid);
    const unsigned bbits = __ballot_sync(0xffffffffu, (bv != 0) & valid);

    float s = 0.0f;
#pragma unroll
    for (int t = 0; t < 27; t++) s += v[t];

    const float center = v[13];           // (x=0, y=0, z) tap
    // 0/1 grid -> sum is an exact small integer; ci in [0, 26].
    const int ci = (int)(s - center + 0.5f);

    const unsigned bits = (center > 0.5f) ? sbits : bbits;
    out[i] = (float)((bits >> ci) & 1u);
}

extern "C" void kernel_launch(void* const* d_in, const int* in_sizes, int n_in,
                              void* d_out, int out_size) {
    const float* grid = (const float*)d_in[0];
    const int* survive_mask = (const int*)d_in[1];
    const int* birth_mask = (const int*)d_in[2];
    float* out = (float*)d_out;

    // out_size = 64: one block, one thread per output cell.
    ca_first_cells_kernel<<<1, 64>>>(grid, survive_mask, birth_mask, out);
}

// round 11
// speedup vs baseline: 1.0559x; 1.0559x over previous
#include <cuda_runtime.h>

// 3D life-like CA step (26-neighbor count, periodic wrap) on a 384^3 float
// grid; output = first out_size (=64) cells of the flattened new grid,
// i.e. cells (x=0, y=0, z=i).
//
// FINAL KERNEL — at the launch-overhead floor. Rounds 4-10 measured
// {4.512..4.832}us for structurally equivalent kernels, including the
// IDENTICAL binary twice (4.608, 4.832): run-to-run noise exceeds all
// remaining kernel-side deltas. DRAM 0.0%, L2 0.3%, all pipes 0.0%.
// Cost model: graph-replay overhead + kernel ramp (~5000 cyc) + one L2
// round trip (36 lines); only the last is kernel-controlled and minimal.
//
// Structure (latency-optimal):
//  - single block, 64 threads, one cell each (best-measured: 4.512us)
//  - 27 independent grid loads per thread, front-batched -> exactly one
//    memory round trip on the critical path
//  - rule tables loaded concurrently by lanes 0..26, packed into register
//    bitmasks via one ballot pair -> lookup is ALU-only, no dependent trip
//  - x=y=0 row offsets compile-time constants; no clamps (0/1 grid makes
//    the neighbor count an exact int in [0,26])
//
// Inputs: d_in[0] grid f32[384^3], d_in[1] survive int32[27],
//         d_in[2] birth int32[27], d_in[3] num_models (unused)
// Output: float32 [out_size]

#define DIM 384

__global__ __launch_bounds__(64, 1)
void ca_first_cells_kernel(const float* __restrict__ grid,
                           const int* __restrict__ survive_mask,
                           const int* __restrict__ birth_mask,
                           float* __restrict__ out) {
    const int i = threadIdx.x;            // cell index, 0..63
    const unsigned lane = (unsigned)i & 31u;

    // Rule-table loads first: independent, resolve inside the same memory
    // round trip as the grid loads.
    const unsigned mi = lane < 27u ? lane : 26u;
    const int sv = survive_mask[mi];
    const int bv = birth_mask[mi];

    // Cell (0, 0, z=i). Low-side wrap only at z=0; high side never wraps
    // (i <= 63 << DIM-1).
    const int z = i;
    const int zm1 = (z == 0) ? (DIM - 1) : (z - 1);
    const int zp1 = z + 1;

    // 9 (x,y)-row base offsets for x=0, y=0: compile-time constants.
    const int rowoff[9] = {
        (DIM - 1) * DIM * DIM + (DIM - 1) * DIM,
        (DIM - 1) * DIM * DIM,
        (DIM - 1) * DIM * DIM + DIM,
        (DIM - 1) * DIM,
        0,
        DIM,
        DIM * DIM + (DIM - 1) * DIM,
        DIM * DIM,
        DIM * DIM + DIM,
    };

    // 27 independent loads, front-batched for max MLP (one latency round).
    float v[27];
#pragma unroll
    for (int r = 0; r < 9; r++) {
        v[r * 3 + 0] = __ldg(&grid[rowoff[r] + zm1]);
        v[r * 3 + 1] = __ldg(&grid[rowoff[r] + z]);
        v[r * 3 + 2] = __ldg(&grid[rowoff[r] + zp1]);
    }

    // Pack rule tables into register bitmasks (per-warp ballots); overlaps
    // with the in-flight grid loads.
    const unsigned valid = (lane < 27u);
    const unsigned sbits = __ballot_sync(0xffffffffu, (sv != 0) & valid);
    const unsigned bbits = __ballot_sync(0xffffffffu, (bv != 0) & valid);

    float s = 0.0f;
#pragma unroll
    for (int t = 0; t < 27; t++) s += v[t];

    const float center = v[13];           // (x=0, y=0, z) tap
    // 0/1 grid -> sum is an exact small integer; ci in [0, 26].
    const int ci = (int)(s - center + 0.5f);

    const unsigned bits = (center > 0.5f) ? sbits : bbits;
    out[i] = (float)((bits >> ci) & 1u);
}

extern "C" void kernel_launch(void* const* d_in, const int* in_sizes, int n_in,
                              void* d_out, int out_size) {
    const float* grid = (const float*)d_in[0];
    const int* survive_mask = (const int*)d_in[1];
    const int* birth_mask = (const int*)d_in[2];
    float* out = (float*)d_out;

    // out_size = 64: one block, one thread per output cell.
    ca_first_cells_kernel<<<1, 64>>>(grid, survive_mask, birth_mask, out);
}